// round 2
// baseline (speedup 1.0000x reference)
#include <cuda_runtime.h>
#include <cstdint>

#define NROWS 4096
#define DIM   512
#define LAT   128
#define TOPK  16

#define BI 128
#define BJ 128
#define KC 16

// -------- scratch (static __device__ arrays; no runtime allocation) --------
__device__ float g_rec_test[NROWS * DIM];
__device__ float g_rec_train[NROWS * DIM];
__device__ float g_dist[(size_t)NROWS * NROWS];   // 64 MB, reused for both matrices
__device__ float g_pos[NROWS];
__device__ float g_neg[NROWS];

// -------- packed f32x2 helpers --------
__device__ __forceinline__ unsigned long long f2add(unsigned long long a, unsigned long long b) {
    unsigned long long r;
    asm("add.rn.f32x2 %0, %1, %2;" : "=l"(r) : "l"(a), "l"(b));
    return r;
}
__device__ __forceinline__ unsigned long long dup2(float x) {
    unsigned long long r;
    unsigned xi = __float_as_uint(x);
    asm("mov.b64 %0, {%1, %1};" : "=l"(r) : "r"(xi));
    return r;
}

// ---------------- GEMM: out[row,:] = lat[row,:] @ W + b ----------------
// grid = NROWS blocks, 128 threads; each thread computes 4 consecutive output cols.
__global__ void gemm_kernel(const float* __restrict__ lat,
                            const float* __restrict__ W,
                            const float* __restrict__ b,
                            float* __restrict__ out) {
    __shared__ float s_lat[LAT];
    int row = blockIdx.x;
    int tx = threadIdx.x;                         // 0..127
    s_lat[tx] = lat[row * LAT + tx];
    __syncthreads();

    float4 acc = *(const float4*)&b[tx * 4];
    const float4* W4 = (const float4*)W;          // [LAT][DIM/4]
    #pragma unroll 8
    for (int l = 0; l < LAT; l++) {
        float a = s_lat[l];
        float4 w = W4[l * (DIM / 4) + tx];
        acc.x += a * w.x; acc.y += a * w.y; acc.z += a * w.z; acc.w += a * w.w;
    }
    *(float4*)&out[(size_t)row * DIM + tx * 4] = acc;
}

// ---------------- L1 cdist: Dout[i,j] = sum_d |X[i,d] - Y[j,d]| ----------------
// CTA tile 128x128, 256 threads (16x16), 8x8 register tile per thread,
// accumulators kept as packed f32x2. Y tile stored NEGATED so diff = a + (-b).
__global__ __launch_bounds__(256, 2) void dist_kernel(
    const float* __restrict__ X, const float* __restrict__ Y,
    float* __restrict__ Dout)
{
    __shared__ float Xs[KC][BI];
    __shared__ float Ys[KC][BJ];

    int t  = threadIdx.x;
    int tx = t & 15;          // j-group
    int ty = t >> 4;          // i-group
    int i0 = blockIdx.y * BI;
    int j0 = blockIdx.x * BJ;

    unsigned long long acc[8][4];
    #pragma unroll
    for (int i = 0; i < 8; i++)
        #pragma unroll
        for (int jp = 0; jp < 4; jp++) acc[i][jp] = 0ULL;   // (0.0f, 0.0f)

    for (int k0 = 0; k0 < DIM; k0 += KC) {
        // ---- load tiles (transposed into [k][row]) ----
        #pragma unroll
        for (int q = 0; q < 2; q++) {
            int s  = t + q * 256;          // 0..511
            int r  = s >> 2;               // tile row 0..127
            int kq = (s & 3) * 4;          // k-quad within chunk
            float4 xv = *(const float4*)&X[(size_t)(i0 + r) * DIM + k0 + kq];
            Xs[kq + 0][r] = xv.x; Xs[kq + 1][r] = xv.y;
            Xs[kq + 2][r] = xv.z; Xs[kq + 3][r] = xv.w;
            float4 yv = *(const float4*)&Y[(size_t)(j0 + r) * DIM + k0 + kq];
            Ys[kq + 0][r] = -yv.x; Ys[kq + 1][r] = -yv.y;
            Ys[kq + 2][r] = -yv.z; Ys[kq + 3][r] = -yv.w;
        }
        __syncthreads();

        #pragma unroll 4
        for (int k = 0; k < KC; k++) {
            float4 a0 = *(const float4*)&Xs[k][ty * 8];
            float4 a1 = *(const float4*)&Xs[k][ty * 8 + 4];
            ulonglong2 bq0 = *(const ulonglong2*)&Ys[k][tx * 8];
            ulonglong2 bq1 = *(const ulonglong2*)&Ys[k][tx * 8 + 4];
            unsigned long long bb[4] = { bq0.x, bq0.y, bq1.x, bq1.y };
            float av[8] = { a0.x, a0.y, a0.z, a0.w, a1.x, a1.y, a1.z, a1.w };
            #pragma unroll
            for (int i = 0; i < 8; i++) {
                unsigned long long a2 = dup2(av[i]);
                #pragma unroll
                for (int jp = 0; jp < 4; jp++) {
                    unsigned long long d = f2add(a2, bb[jp]);   // (a-b) packed
                    d &= 0x7FFFFFFF7FFFFFFFULL;                 // |.| via 2x LOP3 (ALU pipe)
                    acc[i][jp] = f2add(acc[i][jp], d);
                }
            }
        }
        __syncthreads();
    }

    // ---- store 8x8 tile (32B-aligned packed stores) ----
    #pragma unroll
    for (int i = 0; i < 8; i++) {
        size_t base = (size_t)(i0 + ty * 8 + i) * NROWS + (j0 + tx * 8);
        ulonglong2 o0 = { acc[i][0], acc[i][1] };
        ulonglong2 o1 = { acc[i][2], acc[i][3] };
        *(ulonglong2*)&Dout[base]     = o0;
        *(ulonglong2*)&Dout[base + 4] = o1;
    }
}

// ---------------- per-row top-16 smallest distances -> mean of reciprocals ----------------
// one warp per row; per-lane sorted ascending list + 32-way merge.
__global__ void topk_kernel(const float* __restrict__ Dmat, float* __restrict__ out) {
    int warp_global = (blockIdx.x * blockDim.x + threadIdx.x) >> 5;
    int lane = threadIdx.x & 31;
    if (warp_global >= NROWS) return;
    const float* row = Dmat + (size_t)warp_global * NROWS;

    const float INF = __int_as_float(0x7f800000);
    float best[TOPK];
    #pragma unroll
    for (int i = 0; i < TOPK; i++) best[i] = INF;

    for (int c = lane; c < NROWS; c += 32) {
        float v = row[c];
        if (v < best[TOPK - 1]) {
            int p = TOPK - 1;
            while (p > 0 && best[p - 1] > v) { best[p] = best[p - 1]; p--; }
            best[p] = v;
        }
    }

    // merge 32 sorted lists, extract 16 global smallest
    int h = 0;
    float ssum = 0.f;
    #pragma unroll
    for (int r = 0; r < TOPK; r++) {
        float v = (h < TOPK) ? best[h] : INF;
        float m = v;
        #pragma unroll
        for (int off = 16; off; off >>= 1)
            m = fminf(m, __shfl_xor_sync(0xffffffffu, m, off));
        unsigned bal = __ballot_sync(0xffffffffu, v == m);
        if (lane == (__ffs(bal) - 1)) h++;
        ssum += 1.0f / m;
    }
    if (lane == 0) out[warp_global] = ssum * (1.0f / TOPK);
}

// ---------------- final: huber(relu(neg - pos)).mean() ----------------
__global__ void final_kernel(const float* __restrict__ pos,
                             const float* __restrict__ neg,
                             float* __restrict__ out) {
    __shared__ float sred[256];
    float s = 0.f;
    for (int i = threadIdx.x; i < NROWS; i += 256) {
        float l = neg[i] - pos[i];
        l = fmaxf(l, 0.f);
        float h = (l <= 1.0f) ? 0.5f * l * l : (l - 0.5f);
        s += h;
    }
    sred[threadIdx.x] = s;
    __syncthreads();
    for (int st = 128; st; st >>= 1) {
        if (threadIdx.x < st) sred[threadIdx.x] += sred[threadIdx.x + st];
        __syncthreads();
    }
    if (threadIdx.x == 0) out[0] = sred[0] * (1.0f / NROWS);
}

// ---------------- launch ----------------
extern "C" void kernel_launch(void* const* d_in, const int* in_sizes, int n_in,
                              void* d_out, int out_size) {
    const float* gt_vals      = (const float*)d_in[0];   // [4096, 512]
    const float* train_latent = (const float*)d_in[1];   // [4096, 128]
    const float* test_latent  = (const float*)d_in[2];   // [4096, 128]
    const float* W            = (const float*)d_in[3];   // [128, 512]
    const float* b            = (const float*)d_in[4];   // [512]
    float* out = (float*)d_out;

    float *rec_test, *rec_train, *dist, *pos, *neg;
    cudaGetSymbolAddress((void**)&rec_test,  g_rec_test);
    cudaGetSymbolAddress((void**)&rec_train, g_rec_train);
    cudaGetSymbolAddress((void**)&dist,      g_dist);
    cudaGetSymbolAddress((void**)&pos,       g_pos);
    cudaGetSymbolAddress((void**)&neg,       g_neg);

    // 1) decode both latents
    gemm_kernel<<<NROWS, 128>>>(test_latent,  W, b, rec_test);
    gemm_kernel<<<NROWS, 128>>>(train_latent, W, b, rec_train);

    dim3 dgrid(NROWS / BJ, NROWS / BI);

    // 2) positive: cdist(rec_test, gt_vals) -> top-k
    dist_kernel<<<dgrid, 256>>>(rec_test, gt_vals, dist);
    topk_kernel<<<(NROWS * 32) / 256, 256>>>(dist, pos);

    // 3) negative: cdist(rec_test, rec_train) -> top-k
    dist_kernel<<<dgrid, 256>>>(rec_test, rec_train, dist);
    topk_kernel<<<(NROWS * 32) / 256, 256>>>(dist, neg);

    // 4) huber mean
    final_kernel<<<1, 256>>>(pos, neg, out);
}